// round 13
// baseline (speedup 1.0000x reference)
#include <cuda_runtime.h>
#include <cuda_fp16.h>
#include <mma.h>
#include <cstdint>

using namespace nvcuda;

#define BH      64        // batch*heads
#define SEQ     8192
#define DIM     64        // head dim
#define FEAT    128       // 2*DIM feature dim
#define NCHUNK  16
#define CHUNK   (SEQ / NCHUNK)   // 512 rows per reduction chunk
#define SUB     64               // rows staged per pipeline stage
#define NSUB    (CHUNK / SUB)    // 8 stages per CTA
#define BW      80               // partial width: 64 KV cols + 1 Ksum + 15 pad
#define BSW     88               // reduced B width (stride 176B, conflict-free)
#define ONS     4                // out kernel: 128-row super-tiles per CTA

// ---- scratch (device globals: no allocation allowed) ----
__device__ float  g_kv_part[NCHUNK][BH][FEAT][BW];     // per-chunk partial [KV | Ksum | 0]
__device__ __align__(32) __half g_kvh[BH][FEAT][BSW];  // reduced fp16 B (col64 = Ksum)

__device__ __forceinline__ void cp_async16(void* smem_ptr, const void* gptr) {
    uint32_t s = (uint32_t)__cvta_generic_to_shared(smem_ptr);
    asm volatile("cp.async.cg.shared.global [%0], [%1], 16;" :: "r"(s), "l"(gptr));
}
#define CP_COMMIT()  asm volatile("cp.async.commit_group;")
#define CP_WAIT1()   asm volatile("cp.async.wait_group 1;")

// =====================================================================
// Kernel A: partial [KV | Ksum] = phi(K)^T @ [V | 1 | 0] over a chunk.
// cp.async 2-stage raw-fp32 ring -> smem convert -> wmma.
// grid (NCHUNK, BH), 256 threads. Dynamic smem 94208 B (2 CTAs/SM).
// =====================================================================
#define RAWK_OFF  0
#define RAWV_OFF  (2 * SUB * DIM * 4)              // 32768
#define KF_OFF    (RAWV_OFF + 2 * SUB * DIM * 4)   // 65536
#define VS_OFF    (KF_OFF + SUB * 136 * 2)         // 82944
#define A_SMEM    (VS_OFF + SUB * 88 * 2)          // 94208

__global__ __launch_bounds__(256) void kv_partial_kernel(const float* __restrict__ Kin,
                                                         const float* __restrict__ Vin) {
    extern __shared__ __align__(16) char asm_[];
    float* rawK = reinterpret_cast<float*>(asm_ + RAWK_OFF);   // [2][SUB*DIM]
    float* rawV = reinterpret_cast<float*>(asm_ + RAWV_OFF);
    __half (*Kf_s)[136] = reinterpret_cast<__half(*)[136]>(asm_ + KF_OFF);
    __half (*V_s)[88]   = reinterpret_cast<__half(*)[88]>(asm_ + VS_OFF);

    const int chunk = blockIdx.x;
    const int bh    = blockIdx.y;
    const int tid   = threadIdx.x;
    const int warp  = tid >> 5;
    const int wd    = warp >> 1;
    const int wm    = warp & 1;

    // one-time init of the augmented V columns (64 = ones, 65..79 = zeros)
    for (int r = tid; r < SUB; r += 256) {
        V_s[r][64] = __float2half(1.0f);
#pragma unroll
        for (int p = 65; p < 80; p++) V_s[r][p] = __float2half(0.0f);
    }

    wmma::fragment<wmma::accumulator, 16, 16, 16, float> acc[4];
    wmma::fragment<wmma::accumulator, 16, 16, 16, float> accs[2];
#pragma unroll
    for (int i = 0; i < 4; i++) wmma::fill_fragment(acc[i], 0.0f);
#pragma unroll
    for (int i = 0; i < 2; i++) wmma::fill_fragment(accs[i], 0.0f);

    const size_t base = ((size_t)bh * SEQ + (size_t)chunk * CHUNK) * DIM;
    const float4* __restrict__ Kp4 = (const float4*)(Kin + base);
    const float4* __restrict__ Vp4 = (const float4*)(Vin + base);
    const int NF4 = SUB * 16;   // 1024 float4 per stage per matrix

    // prologue: launch stages 0 and 1
#pragma unroll
    for (int st = 0; st < 2; st++) {
#pragma unroll
        for (int j = 0; j < 4; j++) {
            int i = tid + j * 256;
            cp_async16(&rawK[st * (SUB * DIM) + i * 4], &Kp4[st * NF4 + i]);
            cp_async16(&rawV[st * (SUB * DIM) + i * 4], &Vp4[st * NF4 + i]);
        }
        CP_COMMIT();
    }

    for (int sub = 0; sub < NSUB; ++sub) {
        const int p = sub & 1;
        CP_WAIT1();          // stage `sub` landed (<=1 group still pending)
        __syncthreads();

        // convert raw fp32 -> phi(K)/V fp16 tiles
#pragma unroll
        for (int j = 0; j < 4; j++) {
            int i = tid + j * 256;
            int r = i >> 4, c4 = (i & 15) << 2;
            float4 k = *(const float4*)&rawK[p * (SUB * DIM) + i * 4];
            float4 v = *(const float4*)&rawV[p * (SUB * DIM) + i * 4];
            __half2* kp = (__half2*)&Kf_s[r][c4];
            __half2* kn = (__half2*)&Kf_s[r][c4 + 64];
            __half2* vp = (__half2*)&V_s[r][c4];
            kp[0] = __floats2half2_rn(fmaxf(k.x, 0.f), fmaxf(k.y, 0.f));
            kp[1] = __floats2half2_rn(fmaxf(k.z, 0.f), fmaxf(k.w, 0.f));
            kn[0] = __floats2half2_rn(fmaxf(-k.x, 0.f), fmaxf(-k.y, 0.f));
            kn[1] = __floats2half2_rn(fmaxf(-k.z, 0.f), fmaxf(-k.w, 0.f));
            vp[0] = __floats2half2_rn(v.x, v.y);
            vp[1] = __floats2half2_rn(v.z, v.w);
        }
        __syncthreads();     // tiles ready AND raw[p] free for reuse

        // refill raw[p] with stage sub+2 (async; flows under the MMAs)
        if (sub + 2 < NSUB) {
#pragma unroll
            for (int j = 0; j < 4; j++) {
                int i = tid + j * 256;
                cp_async16(&rawK[p * (SUB * DIM) + i * 4], &Kp4[(sub + 2) * NF4 + i]);
                cp_async16(&rawV[p * (SUB * DIM) + i * 4], &Vp4[(sub + 2) * NF4 + i]);
            }
        }
        CP_COMMIT();         // one group per iteration keeps wait-count fixed

        // KV[d,m] += sum_n Kf[n,d] * Vaug[n,m]
#pragma unroll
        for (int ks = 0; ks < SUB / 16; ++ks) {
            wmma::fragment<wmma::matrix_a, 16, 16, 16, __half, wmma::col_major> a0, a1;
            wmma::fragment<wmma::matrix_b, 16, 16, 16, __half, wmma::row_major> b0, b1;
            wmma::load_matrix_sync(a0, &Kf_s[ks * 16][wd * 32],      136);
            wmma::load_matrix_sync(a1, &Kf_s[ks * 16][wd * 32 + 16], 136);
            wmma::load_matrix_sync(b0, &V_s[ks * 16][wm * 32],       88);
            wmma::load_matrix_sync(b1, &V_s[ks * 16][wm * 32 + 16],  88);
            wmma::mma_sync(acc[0], a0, b0, acc[0]);
            wmma::mma_sync(acc[1], a0, b1, acc[1]);
            wmma::mma_sync(acc[2], a1, b0, acc[2]);
            wmma::mma_sync(acc[3], a1, b1, acc[3]);
            if (wm == 0) {
                wmma::fragment<wmma::matrix_b, 16, 16, 16, __half, wmma::row_major> b2;
                wmma::load_matrix_sync(b2, &V_s[ks * 16][64], 88);
                wmma::mma_sync(accs[0], a0, b2, accs[0]);
                wmma::mma_sync(accs[1], a1, b2, accs[1]);
            }
        }
        __syncthreads();     // MMA done reading tiles before next convert
    }

    float* op = &g_kv_part[chunk][bh][0][0];
#pragma unroll
    for (int ti = 0; ti < 2; ++ti)
#pragma unroll
        for (int tj = 0; tj < 2; ++tj)
            wmma::store_matrix_sync(op + (wd * 32 + ti * 16) * BW + wm * 32 + tj * 16,
                                    acc[ti * 2 + tj], BW, wmma::mem_row_major);
    if (wm == 0) {
        wmma::store_matrix_sync(op + (wd * 32) * BW + 64,      accs[0], BW, wmma::mem_row_major);
        wmma::store_matrix_sync(op + (wd * 32 + 16) * BW + 64, accs[1], BW, wmma::mem_row_major);
    }
}

// =====================================================================
// Kernel B: reduce chunk partials -> fp16 B matrix [128 x 88]
// (cols 0..63 = KV, col 64 = Ksum, 65..87 = 0). grid (BH, 8), 256 thr.
// =====================================================================
__global__ __launch_bounds__(256) void kv_reduce_kernel() {
    const int bh    = blockIdx.x;
    const int dbase = blockIdx.y * 16;
    const int tid   = threadIdx.x;

    for (int idx = tid; idx < 16 * 64; idx += 256) {
        int d = dbase + (idx >> 6), m = idx & 63;
        float s = 0.0f;
#pragma unroll
        for (int c = 0; c < NCHUNK; c++) s += g_kv_part[c][bh][d][m];
        g_kvh[bh][d][m] = __float2half(s);
    }
    if (tid < 16) {
        int d = dbase + tid;
        float s = 0.0f;
#pragma unroll
        for (int c = 0; c < NCHUNK; c++) s += g_kv_part[c][bh][d][64];
        g_kvh[bh][d][64] = __float2half(s);
    }
    for (int idx = tid; idx < 16 * 23; idx += 256) {   // zero cols 65..87
        int d = dbase + idx / 23, m = 65 + idx % 23;
        g_kvh[bh][d][m] = __float2half(0.0f);
    }
}

// =====================================================================
// Kernel C: warp-autonomous. 8 warps; warp w owns rows [w*16, w*16+16)
// of a 128-row super-tile, all 72 cols (incl. Ksum col 64).
// grid (SEQ/(128*ONS), BH), 256 threads.
// =====================================================================
#define QF_BYTES  (128 * 136 * 2)   // 34816
#define BS_BYTES  (128 * BSW * 2)   // 22528
#define CS_STRIDE 68
#define CS_BYTES  (8 * 16 * CS_STRIDE * 4)  // 34816
#define C_SMEM    (QF_BYTES + BS_BYTES + CS_BYTES)   // 92160

__global__ __launch_bounds__(256) void out_kernel(const float* __restrict__ Qin,
                                                  float* __restrict__ Out) {
    extern __shared__ __align__(16) char sm[];
    __half (*qf)[136] = reinterpret_cast<__half(*)[136]>(sm);
    __half (*Bs)[BSW] = reinterpret_cast<__half(*)[BSW]>(sm + QF_BYTES);
    float*  csAll     = reinterpret_cast<float*>(sm + QF_BYTES + BS_BYTES);

    const int nt   = blockIdx.x;
    const int bh   = blockIdx.y;
    const int tid  = threadIdx.x;
    const int warp = tid >> 5;
    const int lane = tid & 31;
    const int g    = lane >> 2;
    const int tq   = lane & 3;

    float* cw = csAll + warp * 16 * CS_STRIDE;

    const size_t qbase = ((size_t)bh * SEQ + (size_t)nt * (128 * ONS)) * DIM;
    const float4* __restrict__ Qp4 = (const float4*)(Qin + qbase);
    float* __restrict__ Op = Out + qbase;

    {
        const uint4* __restrict__ Bg = (const uint4*)&g_kvh[bh][0][0];
        uint4* Bsv = (uint4*)&Bs[0][0];
        for (int i = tid; i < BS_BYTES / 16; i += 256) Bsv[i] = Bg[i];
    }

    float4 qreg[8];
#pragma unroll
    for (int j = 0; j < 8; j++) qreg[j] = Qp4[tid + j * 256];

    for (int s = 0; s < ONS; ++s) {
#pragma unroll
        for (int j = 0; j < 8; j++) {
            int i = tid + j * 256;
            int r = i >> 4, c4 = (i & 15) << 2;
            float4 q = qreg[j];
            __half2* qp = (__half2*)&qf[r][c4];
            __half2* qn = (__half2*)&qf[r][c4 + 64];
            qp[0] = __floats2half2_rn(fmaxf(q.x, 0.f), fmaxf(q.y, 0.f));
            qp[1] = __floats2half2_rn(fmaxf(q.z, 0.f), fmaxf(q.w, 0.f));
            qn[0] = __floats2half2_rn(fmaxf(-q.x, 0.f), fmaxf(-q.y, 0.f));
            qn[1] = __floats2half2_rn(fmaxf(-q.z, 0.f), fmaxf(-q.w, 0.f));
        }
        __syncthreads();

        if (s + 1 < ONS) {
#pragma unroll
            for (int j = 0; j < 8; j++)
                qreg[j] = Qp4[(s + 1) * 2048 + tid + j * 256];
        }

        float c[9][4];
#pragma unroll
        for (int f = 0; f < 9; f++)
#pragma unroll
            for (int e = 0; e < 4; e++) c[f][e] = 0.0f;

#pragma unroll
        for (int ks = 0; ks < FEAT / 16; ++ks) {
            uint32_t a[4];
            {
                uint32_t addr = (uint32_t)__cvta_generic_to_shared(
                    &qf[warp * 16 + (lane & 15)][ks * 16 + (lane >> 4) * 8]);
                asm volatile("ldmatrix.sync.aligned.m8n8.x4.shared.b16 {%0,%1,%2,%3}, [%4];"
                             : "=r"(a[0]), "=r"(a[1]), "=r"(a[2]), "=r"(a[3]) : "r"(addr));
            }
#pragma unroll
            for (int h = 0; h < 4; h++) {
                uint32_t b[4];
                uint32_t addr = (uint32_t)__cvta_generic_to_shared(
                    &Bs[ks * 16 + (lane & 15)][h * 16 + (lane >> 4) * 8]);
                asm volatile("ldmatrix.sync.aligned.m8n8.x4.trans.shared.b16 {%0,%1,%2,%3}, [%4];"
                             : "=r"(b[0]), "=r"(b[1]), "=r"(b[2]), "=r"(b[3]) : "r"(addr));
                asm volatile("mma.sync.aligned.m16n8k16.row.col.f32.f16.f16.f32 "
                             "{%0,%1,%2,%3},{%4,%5,%6,%7},{%8,%9},{%0,%1,%2,%3};"
                             : "+f"(c[h*2][0]), "+f"(c[h*2][1]), "+f"(c[h*2][2]), "+f"(c[h*2][3])
                             : "r"(a[0]), "r"(a[1]), "r"(a[2]), "r"(a[3]), "r"(b[0]), "r"(b[1]));
                asm volatile("mma.sync.aligned.m16n8k16.row.col.f32.f16.f16.f32 "
                             "{%0,%1,%2,%3},{%4,%5,%6,%7},{%8,%9},{%0,%1,%2,%3};"
                             : "+f"(c[h*2+1][0]), "+f"(c[h*2+1][1]), "+f"(c[h*2+1][2]), "+f"(c[h*2+1][3])
                             : "r"(a[0]), "r"(a[1]), "r"(a[2]), "r"(a[3]), "r"(b[2]), "r"(b[3]));
            }
            {   // Ksum tile: cols 64..71 (col 64 = normalizer)
                uint32_t b[2];
                uint32_t addr = (uint32_t)__cvta_generic_to_shared(
                    &Bs[ks * 16 + (lane & 15)][64]);
                asm volatile("ldmatrix.sync.aligned.m8n8.x2.trans.shared.b16 {%0,%1}, [%2];"
                             : "=r"(b[0]), "=r"(b[1]) : "r"(addr));
                asm volatile("mma.sync.aligned.m16n8k16.row.col.f32.f16.f16.f32 "
                             "{%0,%1,%2,%3},{%4,%5,%6,%7},{%8,%9},{%0,%1,%2,%3};"
                             : "+f"(c[8][0]), "+f"(c[8][1]), "+f"(c[8][2]), "+f"(c[8][3])
                             : "r"(a[0]), "r"(a[1]), "r"(a[2]), "r"(a[3]), "r"(b[0]), "r"(b[1]));
            }
        }

        float n_lo = __shfl_sync(0xffffffffu, c[8][0], lane & ~3);
        float n_hi = __shfl_sync(0xffffffffu, c[8][2], lane & ~3);
        float inv_lo = 1.0f / (n_lo + 1e-6f);
        float inv_hi = 1.0f / (n_hi + 1e-6f);

#pragma unroll
        for (int f = 0; f < 8; f++) {
            int col = f * 8 + 2 * tq;
            *(float2*)&cw[g * CS_STRIDE + col] =
                make_float2(c[f][0] * inv_lo, c[f][1] * inv_lo);
            *(float2*)&cw[(g + 8) * CS_STRIDE + col] =
                make_float2(c[f][2] * inv_hi, c[f][3] * inv_hi);
        }
        __syncwarp();

        {
            float* orow = Op + ((size_t)s * 128 + warp * 16) * DIM;
#pragma unroll
            for (int it = 0; it < 8; ++it) {
                int idx = lane + it * 32;
                int r = idx >> 4, c4 = (idx & 15) << 2;
                float4 v = *(float4*)&cw[r * CS_STRIDE + c4];
                *(float4*)&orow[(size_t)r * DIM + c4] = v;
            }
        }
        __syncthreads();
    }
}

// =====================================================================
extern "C" void kernel_launch(void* const* d_in, const int* in_sizes, int n_in,
                              void* d_out, int out_size) {
    const float* Q = (const float*)d_in[0];
    const float* K = (const float*)d_in[1];
    const float* V = (const float*)d_in[2];
    float* O = (float*)d_out;

    static int smem_set = 0;
    if (!smem_set) {
        cudaFuncSetAttribute(kv_partial_kernel, cudaFuncAttributeMaxDynamicSharedMemorySize, A_SMEM);
        cudaFuncSetAttribute(out_kernel, cudaFuncAttributeMaxDynamicSharedMemorySize, C_SMEM);
        smem_set = 1;
    }

    dim3 gA(NCHUNK, BH);
    kv_partial_kernel<<<gA, 256, A_SMEM>>>(K, V);
    dim3 gB(BH, 8);
    kv_reduce_kernel<<<gB, 256>>>();
    dim3 gC(SEQ / (128 * ONS), BH);
    out_kernel<<<gC, 256, C_SMEM>>>(Q, O);
}

// round 14
// speedup vs baseline: 1.3547x; 1.3547x over previous
#include <cuda_runtime.h>
#include <cuda_fp16.h>
#include <mma.h>
#include <cstdint>

using namespace nvcuda;

#define BH      64        // batch*heads
#define SEQ     8192
#define DIM     64        // head dim
#define FEAT    128       // 2*DIM feature dim
#define NCHUNK  16
#define CHUNK   (SEQ / NCHUNK)   // 512 rows per reduction chunk
#define SUB     64               // rows per pipeline stage
#define NSUB    (CHUNK / SUB)    // 8 stages per CTA
#define BW      80               // partial width: 64 KV cols + 1 Ksum + 15 pad
#define BSW     88               // reduced B width (stride 176B, conflict-free)
#define ONS     2                // out kernel: 128-row super-tiles per CTA

// ---- scratch (device globals: no allocation allowed) ----
__device__ float  g_kv_part[NCHUNK][BH][FEAT][BW];     // per-chunk partial [KV | Ksum | 0]
__device__ __align__(32) __half g_kvh[BH][FEAT][BSW];  // reduced fp16 B (col64 = Ksum)

// =====================================================================
// Kernel A: partial [KV | Ksum] = phi(K)^T @ [V | 1 | 0] over a chunk.
// Register prefetch + DOUBLE-BUFFERED fp16 tiles -> 1 barrier per stage.
// grid (NCHUNK, BH), 256 threads. Dynamic smem 57344 B.
// =====================================================================
#define KF_STRIDE 136
#define VV_STRIDE 88
#define KF_BUF    (SUB * KF_STRIDE * 2)    // 17408 B per buffer
#define VV_BUF    (SUB * VV_STRIDE * 2)    // 11264 B per buffer
#define A_SMEM    (2 * KF_BUF + 2 * VV_BUF)  // 57344

__global__ __launch_bounds__(256) void kv_partial_kernel(const float* __restrict__ Kin,
                                                         const float* __restrict__ Vin) {
    extern __shared__ __align__(16) char asm_[];
    // layout: Kf[0], Kf[1], V[0], V[1]
    __half* KfB = reinterpret_cast<__half*>(asm_);
    __half* VB  = reinterpret_cast<__half*>(asm_ + 2 * KF_BUF);

    const int chunk = blockIdx.x;
    const int bh    = blockIdx.y;
    const int tid   = threadIdx.x;
    const int warp  = tid >> 5;
    const int wd    = warp >> 1;   // 0..3 -> 32 feature rows each
    const int wm    = warp & 1;    // 0..1 -> 32 V cols each

    // one-time init of augmented V cols (64 = ones, 65..79 = zeros), both buffers
    for (int r = tid; r < 2 * SUB; r += 256) {
        __half* vrow = VB + r * VV_STRIDE;   // rows 0..63 buf0, 64..127 buf1
        vrow[64] = __float2half(1.0f);
#pragma unroll
        for (int p = 65; p < 80; p++) vrow[p] = __float2half(0.0f);
    }

    wmma::fragment<wmma::accumulator, 16, 16, 16, float> acc[4];
    wmma::fragment<wmma::accumulator, 16, 16, 16, float> accs[2];
#pragma unroll
    for (int i = 0; i < 4; i++) wmma::fill_fragment(acc[i], 0.0f);
#pragma unroll
    for (int i = 0; i < 2; i++) wmma::fill_fragment(accs[i], 0.0f);

    const size_t base = ((size_t)bh * SEQ + (size_t)chunk * CHUNK) * DIM;
    const float4* __restrict__ Kp4 = (const float4*)(Kin + base);
    const float4* __restrict__ Vp4 = (const float4*)(Vin + base);

    const int NF4 = SUB * 16;          // 1024 float4 per stage per matrix
    float4 kreg[4], vreg[4];

    // prefetch stage 0
#pragma unroll
    for (int j = 0; j < 4; j++) {
        int i = tid + j * 256;
        kreg[j] = Kp4[i];
        vreg[j] = Vp4[i];
    }

    for (int sub = 0; sub < NSUB; ++sub) {
        const int p = sub & 1;
        __half* Kf_s = KfB + p * (SUB * KF_STRIDE);
        __half* V_s  = VB  + p * (SUB * VV_STRIDE);

        // convert register buffer -> tiles[p] (phi transform).
        // Safe without a pre-barrier: all warps finished MMA(sub-1) on buffer p
        // before the barrier of iteration sub-1... (drift argument: buffer p's
        // last readers were MMA(sub-2), complete before barrier(sub-1), which
        // every warp passed before its convert here.)
#pragma unroll
        for (int j = 0; j < 4; j++) {
            int i = tid + j * 256;
            int r = i >> 4, c4 = (i & 15) << 2;
            float4 k = kreg[j], v = vreg[j];
            __half2* kp = (__half2*)&Kf_s[r * KF_STRIDE + c4];
            __half2* kn = (__half2*)&Kf_s[r * KF_STRIDE + c4 + 64];
            __half2* vp = (__half2*)&V_s[r * VV_STRIDE + c4];
            kp[0] = __floats2half2_rn(fmaxf(k.x, 0.f), fmaxf(k.y, 0.f));
            kp[1] = __floats2half2_rn(fmaxf(k.z, 0.f), fmaxf(k.w, 0.f));
            kn[0] = __floats2half2_rn(fmaxf(-k.x, 0.f), fmaxf(-k.y, 0.f));
            kn[1] = __floats2half2_rn(fmaxf(-k.z, 0.f), fmaxf(-k.w, 0.f));
            vp[0] = __floats2half2_rn(v.x, v.y);
            vp[1] = __floats2half2_rn(v.z, v.w);
        }
        __syncthreads();   // the ONLY barrier: tiles[p] complete for all warps

        // prefetch next stage; latency hides under the MMAs
        if (sub + 1 < NSUB) {
#pragma unroll
            for (int j = 0; j < 4; j++) {
                int i = tid + j * 256;
                kreg[j] = Kp4[(sub + 1) * NF4 + i];
                vreg[j] = Vp4[(sub + 1) * NF4 + i];
            }
        }

        // KV[d,m] += sum_n Kf[n,d] * Vaug[n,m]
#pragma unroll
        for (int ks = 0; ks < SUB / 16; ++ks) {
            wmma::fragment<wmma::matrix_a, 16, 16, 16, __half, wmma::col_major> a0, a1;
            wmma::fragment<wmma::matrix_b, 16, 16, 16, __half, wmma::row_major> b0, b1;
            wmma::load_matrix_sync(a0, &Kf_s[ks * 16 * KF_STRIDE + wd * 32],      KF_STRIDE);
            wmma::load_matrix_sync(a1, &Kf_s[ks * 16 * KF_STRIDE + wd * 32 + 16], KF_STRIDE);
            wmma::load_matrix_sync(b0, &V_s[ks * 16 * VV_STRIDE + wm * 32],       VV_STRIDE);
            wmma::load_matrix_sync(b1, &V_s[ks * 16 * VV_STRIDE + wm * 32 + 16],  VV_STRIDE);
            wmma::mma_sync(acc[0], a0, b0, acc[0]);
            wmma::mma_sync(acc[1], a0, b1, acc[1]);
            wmma::mma_sync(acc[2], a1, b0, acc[2]);
            wmma::mma_sync(acc[3], a1, b1, acc[3]);
            if (wm == 0) {
                wmma::fragment<wmma::matrix_b, 16, 16, 16, __half, wmma::row_major> b2;
                wmma::load_matrix_sync(b2, &V_s[ks * 16 * VV_STRIDE + 64], VV_STRIDE);
                wmma::mma_sync(accs[0], a0, b2, accs[0]);
                wmma::mma_sync(accs[1], a1, b2, accs[1]);
            }
        }
        // no trailing barrier: next convert targets the other buffer
    }

    float* op = &g_kv_part[chunk][bh][0][0];
#pragma unroll
    for (int ti = 0; ti < 2; ++ti)
#pragma unroll
        for (int tj = 0; tj < 2; ++tj)
            wmma::store_matrix_sync(op + (wd * 32 + ti * 16) * BW + wm * 32 + tj * 16,
                                    acc[ti * 2 + tj], BW, wmma::mem_row_major);
    if (wm == 0) {
        wmma::store_matrix_sync(op + (wd * 32) * BW + 64,      accs[0], BW, wmma::mem_row_major);
        wmma::store_matrix_sync(op + (wd * 32 + 16) * BW + 64, accs[1], BW, wmma::mem_row_major);
    }
}

// =====================================================================
// Kernel B: reduce chunk partials -> fp16 B matrix [128 x 88]
// (cols 0..63 = KV, col 64 = Ksum, 65..87 = 0). grid (BH, 8), 256 thr.
// =====================================================================
__global__ __launch_bounds__(256) void kv_reduce_kernel() {
    const int bh    = blockIdx.x;
    const int dbase = blockIdx.y * 16;
    const int tid   = threadIdx.x;

    for (int idx = tid; idx < 16 * 64; idx += 256) {
        int d = dbase + (idx >> 6), m = idx & 63;
        float s = 0.0f;
#pragma unroll
        for (int c = 0; c < NCHUNK; c++) s += g_kv_part[c][bh][d][m];
        g_kvh[bh][d][m] = __float2half(s);
    }
    if (tid < 16) {
        int d = dbase + tid;
        float s = 0.0f;
#pragma unroll
        for (int c = 0; c < NCHUNK; c++) s += g_kv_part[c][bh][d][64];
        g_kvh[bh][d][64] = __float2half(s);
    }
    for (int idx = tid; idx < 16 * 23; idx += 256) {   // zero cols 65..87
        int d = dbase + idx / 23, m = 65 + idx % 23;
        g_kvh[bh][d][m] = __float2half(0.0f);
    }
}

// =====================================================================
// Kernel C: warp-autonomous, qf double-buffered, cs aliased onto the
// warp's own qf strip (each warp only reads its own 16 qf rows).
// 1 __syncthreads per 128-row super-tile. grid (SEQ/(128*ONS), BH), 256 thr.
// Dynamic smem: qf[2][128][136] fp16 (69632) + Bs[128][88] fp16 (22528)
// =====================================================================
#define QF_STRIDE 136
#define QF_BUF    (128 * QF_STRIDE * 2)     // 34816 B per buffer
#define BS_BYTES  (128 * BSW * 2)           // 22528
#define CS_STRIDE 68                        // floats; 68*4 == 136*2 bytes per row
#define C_SMEM    (2 * QF_BUF + BS_BYTES)   // 92160

__global__ __launch_bounds__(256) void out_kernel(const float* __restrict__ Qin,
                                                  float* __restrict__ Out) {
    extern __shared__ __align__(16) char sm[];
    __half* qfB       = reinterpret_cast<__half*>(sm);
    __half (*Bs)[BSW] = reinterpret_cast<__half(*)[BSW]>(sm + 2 * QF_BUF);

    const int nt   = blockIdx.x;
    const int bh   = blockIdx.y;
    const int tid  = threadIdx.x;
    const int warp = tid >> 5;
    const int lane = tid & 31;
    const int g    = lane >> 2;
    const int tq   = lane & 3;

    const size_t qbase = ((size_t)bh * SEQ + (size_t)nt * (128 * ONS)) * DIM;
    const float4* __restrict__ Qp4 = (const float4*)(Qin + qbase);
    float* __restrict__ Op = Out + qbase;

    // stage B once per CTA (coalesced uint4)
    {
        const uint4* __restrict__ Bg = (const uint4*)&g_kvh[bh][0][0];
        uint4* Bsv = (uint4*)&Bs[0][0];
        for (int i = tid; i < BS_BYTES / 16; i += 256) Bsv[i] = Bg[i];
    }

    float4 qreg[8];
#pragma unroll
    for (int j = 0; j < 8; j++) qreg[j] = Qp4[tid + j * 256];

    for (int s = 0; s < ONS; ++s) {
        const int p = s & 1;
        __half* qf = qfB + p * (128 * QF_STRIDE);

        // ---- convert qreg -> qf[p] (phi transform), 128 rows ----
        // Safe: buffer p's last readers (MMA/epilogue of iter s-2 in own rows,
        // MMA of s-2 across warps) all completed before barrier(s-1).
#pragma unroll
        for (int j = 0; j < 8; j++) {
            int i = tid + j * 256;
            int r = i >> 4, c4 = (i & 15) << 2;
            float4 q = qreg[j];
            __half2* qp = (__half2*)&qf[r * QF_STRIDE + c4];
            __half2* qn = (__half2*)&qf[r * QF_STRIDE + c4 + 64];
            qp[0] = __floats2half2_rn(fmaxf(q.x, 0.f), fmaxf(q.y, 0.f));
            qp[1] = __floats2half2_rn(fmaxf(q.z, 0.f), fmaxf(q.w, 0.f));
            qn[0] = __floats2half2_rn(fmaxf(-q.x, 0.f), fmaxf(-q.y, 0.f));
            qn[1] = __floats2half2_rn(fmaxf(-q.z, 0.f), fmaxf(-q.w, 0.f));
        }
        __syncthreads();   // the ONLY barrier: qf[p] complete (covers Bs on s==0)

        // prefetch next super-tile's Q; lands during the MMA stretch
        if (s + 1 < ONS) {
#pragma unroll
            for (int j = 0; j < 8; j++)
                qreg[j] = Qp4[(s + 1) * 2048 + tid + j * 256];
        }

        // ---- warp-local MMA: 16 rows x 72 cols over k=128 ----
        float c[9][4];
#pragma unroll
        for (int f = 0; f < 9; f++)
#pragma unroll
            for (int e = 0; e < 4; e++) c[f][e] = 0.0f;

#pragma unroll
        for (int ks = 0; ks < FEAT / 16; ++ks) {
            uint32_t a[4];
            {
                uint32_t addr = (uint32_t)__cvta_generic_to_shared(
                    &qf[(warp * 16 + (lane & 15)) * QF_STRIDE + ks * 16 + (lane >> 4) * 8]);
                asm volatile("ldmatrix.sync.aligned.m8n8.x4.shared.b16 {%0,%1,%2,%3}, [%4];"
                             : "=r"(a[0]), "=r"(a[1]), "=r"(a[2]), "=r"(a[3]) : "r"(addr));
            }
#pragma unroll
            for (int h = 0; h < 4; h++) {
                uint32_t b[4];
                uint32_t addr = (uint32_t)__cvta_generic_to_shared(
                    &Bs[ks * 16 + (lane & 15)][h * 16 + (lane >> 4) * 8]);
                asm volatile("ldmatrix.sync.aligned.m8n8.x4.trans.shared.b16 {%0,%1,%2,%3}, [%4];"
                             : "=r"(b[0]), "=r"(b[1]), "=r"(b[2]), "=r"(b[3]) : "r"(addr));
                asm volatile("mma.sync.aligned.m16n8k16.row.col.f32.f16.f16.f32 "
                             "{%0,%1,%2,%3},{%4,%5,%6,%7},{%8,%9},{%0,%1,%2,%3};"
                             : "+f"(c[h*2][0]), "+f"(c[h*2][1]), "+f"(c[h*2][2]), "+f"(c[h*2][3])
                             : "r"(a[0]), "r"(a[1]), "r"(a[2]), "r"(a[3]), "r"(b[0]), "r"(b[1]));
                asm volatile("mma.sync.aligned.m16n8k16.row.col.f32.f16.f16.f32 "
                             "{%0,%1,%2,%3},{%4,%5,%6,%7},{%8,%9},{%0,%1,%2,%3};"
                             : "+f"(c[h*2+1][0]), "+f"(c[h*2+1][1]), "+f"(c[h*2+1][2]), "+f"(c[h*2+1][3])
                             : "r"(a[0]), "r"(a[1]), "r"(a[2]), "r"(a[3]), "r"(b[2]), "r"(b[3]));
            }
            {   // Ksum tile: cols 64..71 (col 64 = normalizer)
                uint32_t b[2];
                uint32_t addr = (uint32_t)__cvta_generic_to_shared(
                    &Bs[ks * 16 + (lane & 15)][64]);
                asm volatile("ldmatrix.sync.aligned.m8n8.x2.trans.shared.b16 {%0,%1}, [%2];"
                             : "=r"(b[0]), "=r"(b[1]) : "r"(addr));
                asm volatile("mma.sync.aligned.m16n8k16.row.col.f32.f16.f16.f32 "
                             "{%0,%1,%2,%3},{%4,%5,%6,%7},{%8,%9},{%0,%1,%2,%3};"
                             : "+f"(c[8][0]), "+f"(c[8][1]), "+f"(c[8][2]), "+f"(c[8][3])
                             : "r"(a[0]), "r"(a[1]), "r"(a[2]), "r"(a[3]), "r"(b[0]), "r"(b[1]));
            }
        }

        // ---- normalizer from own accumulators (col 64 held by tq==0) ----
        float n_lo = __shfl_sync(0xffffffffu, c[8][0], lane & ~3);
        float n_hi = __shfl_sync(0xffffffffu, c[8][2], lane & ~3);
        float inv_lo = 1.0f / (n_lo + 1e-6f);
        float inv_hi = 1.0f / (n_hi + 1e-6f);

        // ---- epilogue: cs strip ALIASES this warp's own qf[p] rows ----
        // (MMA done reading them; 16*136 halves == 16*68 floats, exact fit)
        float* cw = reinterpret_cast<float*>(qf + (warp * 16) * QF_STRIDE);
#pragma unroll
        for (int f = 0; f < 8; f++) {
            int col = f * 8 + 2 * tq;
            *(float2*)&cw[g * CS_STRIDE + col] =
                make_float2(c[f][0] * inv_lo, c[f][1] * inv_lo);
            *(float2*)&cw[(g + 8) * CS_STRIDE + col] =
                make_float2(c[f][2] * inv_hi, c[f][3] * inv_hi);
        }
        __syncwarp();

        // coalesced float4 read-back + STG (16 rows x 256B contiguous)
        {
            float* orow = Op + ((size_t)s * 128 + warp * 16) * DIM;
#pragma unroll
            for (int it = 0; it < 8; ++it) {
                int idx = lane + it * 32;
                int r = idx >> 4, c4 = (idx & 15) << 2;
                float4 v = *(float4*)&cw[r * CS_STRIDE + c4];
                *(float4*)&orow[(size_t)r * DIM + c4] = v;
            }
        }
        // no trailing barrier: next convert targets the other qf buffer
    }
}

// =====================================================================
extern "C" void kernel_launch(void* const* d_in, const int* in_sizes, int n_in,
                              void* d_out, int out_size) {
    const float* Q = (const float*)d_in[0];
    const float* K = (const float*)d_in[1];
    const float* V = (const float*)d_in[2];
    float* O = (float*)d_out;

    static int smem_set = 0;
    if (!smem_set) {
        cudaFuncSetAttribute(kv_partial_kernel, cudaFuncAttributeMaxDynamicSharedMemorySize, A_SMEM);
        cudaFuncSetAttribute(out_kernel, cudaFuncAttributeMaxDynamicSharedMemorySize, C_SMEM);
        smem_set = 1;
    }

    dim3 gA(NCHUNK, BH);
    kv_partial_kernel<<<gA, 256, A_SMEM>>>(K, V);
    dim3 gB(BH, 8);
    kv_reduce_kernel<<<gB, 256>>>();
    dim3 gC(SEQ / (128 * ONS), BH);
    out_kernel<<<gC, 256, C_SMEM>>>(Q, O);
}

// round 16
// speedup vs baseline: 1.4160x; 1.0453x over previous
#include <cuda_runtime.h>
#include <cuda_fp16.h>
#include <mma.h>
#include <cstdint>

using namespace nvcuda;

#define BH      64        // batch*heads
#define SEQ     8192
#define DIM     64        // head dim
#define FEAT    128       // 2*DIM feature dim
#define NCHUNK  16
#define CHUNK   (SEQ / NCHUNK)   // 512 rows per reduction chunk
#define SUB     64               // rows staged in smem per iteration
#define BW      80               // partial width: 64 KV cols + 1 Ksum + 15 pad
#define BSW     88               // reduced B width (stride 176B, conflict-free)
#define ONS     2                // out kernel: 128-row super-tiles per CTA

// ---- scratch (device globals: no allocation allowed) ----
__device__ __align__(16) __half g_kv_part[NCHUNK][BH][FEAT][BW];  // fp16 partials
__device__ __align__(32) __half g_kvh[BH][FEAT][BSW];             // reduced fp16 B (col64 = Ksum)

// =====================================================================
// Kernel A: partial [KV | Ksum] = phi(K)^T @ [V | 1 | 0] over a chunk.
// Register double-buffered pipeline (validated R12 structure).
// Epilogue: per-tile smem bounce -> fp16 STG.128.
// grid (NCHUNK, BH), 256 threads.
// =====================================================================
__global__ __launch_bounds__(256) void kv_partial_kernel(const float* __restrict__ Kin,
                                                         const float* __restrict__ Vin) {
    const int chunk = blockIdx.x;
    const int bh    = blockIdx.y;
    const int tid   = threadIdx.x;
    const int warp  = tid >> 5;
    const int lane  = tid & 31;
    const int wd    = warp >> 1;   // 0..3 -> 32 feature rows each
    const int wm    = warp & 1;    // 0..1 -> 32 V cols each

    __shared__ __align__(16) __half Kf_s[SUB][136];
    __shared__ __align__(16) __half V_s [SUB][88];

    for (int r = tid; r < SUB; r += 256) {
        V_s[r][64] = __float2half(1.0f);
#pragma unroll
        for (int p = 65; p < 80; p++) V_s[r][p] = __float2half(0.0f);
    }

    wmma::fragment<wmma::accumulator, 16, 16, 16, float> acc[4];
    wmma::fragment<wmma::accumulator, 16, 16, 16, float> accs[2];
#pragma unroll
    for (int i = 0; i < 4; i++) wmma::fill_fragment(acc[i], 0.0f);
#pragma unroll
    for (int i = 0; i < 2; i++) wmma::fill_fragment(accs[i], 0.0f);

    const size_t base = ((size_t)bh * SEQ + (size_t)chunk * CHUNK) * DIM;
    const float4* __restrict__ Kp4 = (const float4*)(Kin + base);
    const float4* __restrict__ Vp4 = (const float4*)(Vin + base);

    const int NF4 = SUB * 16;
    float4 kreg[4], vreg[4];

#pragma unroll
    for (int j = 0; j < 4; j++) {
        int i = tid + j * 256;
        kreg[j] = Kp4[i];
        vreg[j] = Vp4[i];
    }

    for (int sub = 0; sub < CHUNK / SUB; ++sub) {
#pragma unroll
        for (int j = 0; j < 4; j++) {
            int i = tid + j * 256;
            int r = i >> 4, c4 = (i & 15) << 2;
            float4 k = kreg[j], v = vreg[j];
            __half2* kp = (__half2*)&Kf_s[r][c4];
            __half2* kn = (__half2*)&Kf_s[r][c4 + 64];
            __half2* vp = (__half2*)&V_s[r][c4];
            kp[0] = __floats2half2_rn(fmaxf(k.x, 0.f), fmaxf(k.y, 0.f));
            kp[1] = __floats2half2_rn(fmaxf(k.z, 0.f), fmaxf(k.w, 0.f));
            kn[0] = __floats2half2_rn(fmaxf(-k.x, 0.f), fmaxf(-k.y, 0.f));
            kn[1] = __floats2half2_rn(fmaxf(-k.z, 0.f), fmaxf(-k.w, 0.f));
            vp[0] = __floats2half2_rn(v.x, v.y);
            vp[1] = __floats2half2_rn(v.z, v.w);
        }
        __syncthreads();

        if (sub + 1 < CHUNK / SUB) {
#pragma unroll
            for (int j = 0; j < 4; j++) {
                int i = tid + j * 256;
                kreg[j] = Kp4[(sub + 1) * NF4 + i];
                vreg[j] = Vp4[(sub + 1) * NF4 + i];
            }
        }

#pragma unroll
        for (int ks = 0; ks < SUB / 16; ++ks) {
            wmma::fragment<wmma::matrix_a, 16, 16, 16, __half, wmma::col_major> a0, a1;
            wmma::fragment<wmma::matrix_b, 16, 16, 16, __half, wmma::row_major> b0, b1;
            wmma::load_matrix_sync(a0, &Kf_s[ks * 16][wd * 32],      136);
            wmma::load_matrix_sync(a1, &Kf_s[ks * 16][wd * 32 + 16], 136);
            wmma::load_matrix_sync(b0, &V_s[ks * 16][wm * 32],       88);
            wmma::load_matrix_sync(b1, &V_s[ks * 16][wm * 32 + 16],  88);
            wmma::mma_sync(acc[0], a0, b0, acc[0]);
            wmma::mma_sync(acc[1], a0, b1, acc[1]);
            wmma::mma_sync(acc[2], a1, b0, acc[2]);
            wmma::mma_sync(acc[3], a1, b1, acc[3]);
            if (wm == 0) {
                wmma::fragment<wmma::matrix_b, 16, 16, 16, __half, wmma::row_major> b2;
                wmma::load_matrix_sync(b2, &V_s[ks * 16][64], 88);
                wmma::mma_sync(accs[0], a0, b2, accs[0]);
                wmma::mma_sync(accs[1], a1, b2, accs[1]);
            }
        }
        __syncthreads();
    }

    // ---- epilogue: fp32 accum -> per-warp smem scratch -> fp16 STG.128 ----
    // Kf_s is free (last loop iteration ended with __syncthreads).
    float* scr = reinterpret_cast<float*>(&Kf_s[0][0]) + warp * 264;  // 8x1056B < 17408B
    __half* op = &g_kv_part[chunk][bh][0][0];
    const int r_  = lane >> 1;          // 0..15: tile row handled by this lane
    const int c0_ = (lane & 1) * 8;     // 0 or 8: 8-col half of the 16-col tile

#pragma unroll
    for (int ti = 0; ti < 2; ++ti)
#pragma unroll
        for (int tj = 0; tj < 2; ++tj) {
            wmma::store_matrix_sync(scr, acc[ti * 2 + tj], 16, wmma::mem_row_major);
            __syncwarp();
            __half2 h[4];
#pragma unroll
            for (int t = 0; t < 4; t++)
                h[t] = __floats2half2_rn(scr[r_ * 16 + c0_ + 2 * t],
                                         scr[r_ * 16 + c0_ + 2 * t + 1]);
            *(uint4*)&op[(size_t)(wd * 32 + ti * 16 + r_) * BW + wm * 32 + tj * 16 + c0_] =
                *(uint4*)h;
            __syncwarp();
        }
    if (wm == 0) {
#pragma unroll
        for (int ti = 0; ti < 2; ++ti) {
            wmma::store_matrix_sync(scr, accs[ti], 16, wmma::mem_row_major);
            __syncwarp();
            __half2 h[4];
#pragma unroll
            for (int t = 0; t < 4; t++)
                h[t] = __floats2half2_rn(scr[r_ * 16 + c0_ + 2 * t],
                                         scr[r_ * 16 + c0_ + 2 * t + 1]);
            *(uint4*)&op[(size_t)(wd * 32 + ti * 16 + r_) * BW + 64 + c0_] = *(uint4*)h;
            __syncwarp();
        }
    }
}

// =====================================================================
// Kernel B: reduce fp16 chunk partials -> fp16 B matrix [128 x 88]
// (cols 0..63 = KV, col 64 = Ksum, 65..87 = 0). grid (BH, 8), 256 thr.
// =====================================================================
__global__ __launch_bounds__(256) void kv_reduce_kernel() {
    const int bh    = blockIdx.x;
    const int dbase = blockIdx.y * 16;
    const int tid   = threadIdx.x;

    // 33 half2 units per row: cols 0..63 (32 units) + cols 64/65 (unit 32)
    for (int idx = tid; idx < 16 * 33; idx += 256) {
        int d = dbase + idx / 33, m2 = idx % 33;
        float2 s = make_float2(0.0f, 0.0f);
#pragma unroll
        for (int c = 0; c < NCHUNK; c++) {
            float2 f = __half22float2(*(const __half2*)&g_kv_part[c][bh][d][m2 * 2]);
            s.x += f.x; s.y += f.y;
        }
        if (m2 < 32) {
            *(__half2*)&g_kvh[bh][d][m2 * 2] = __floats2half2_rn(s.x, s.y);
        } else {
            *(__half2*)&g_kvh[bh][d][64] = __floats2half2_rn(s.x, 0.0f);  // Ksum | 0
        }
    }
    for (int idx = tid; idx < 16 * 22; idx += 256) {   // zero cols 66..87
        int d = dbase + idx / 22, m = 66 + idx % 22;
        g_kvh[bh][d][m] = __float2half(0.0f);
    }
}

// =====================================================================
// Kernel C: warp-autonomous, qf double-buffered, cs aliased onto the
// warp's own qf strip. 1 __syncthreads per 128-row super-tile.
// grid (SEQ/(128*ONS), BH), 256 threads. (validated R14 version)
// =====================================================================
#define QF_STRIDE 136
#define QF_BUF    (128 * QF_STRIDE * 2)     // 34816 B per buffer
#define BS_BYTES  (128 * BSW * 2)           // 22528
#define CS_STRIDE 68
#define C_SMEM    (2 * QF_BUF + BS_BYTES)   // 92160

__global__ __launch_bounds__(256) void out_kernel(const float* __restrict__ Qin,
                                                  float* __restrict__ Out) {
    extern __shared__ __align__(16) char sm[];
    __half* qfB       = reinterpret_cast<__half*>(sm);
    __half (*Bs)[BSW] = reinterpret_cast<__half(*)[BSW]>(sm + 2 * QF_BUF);

    const int nt   = blockIdx.x;
    const int bh   = blockIdx.y;
    const int tid  = threadIdx.x;
    const int warp = tid >> 5;
    const int lane = tid & 31;
    const int g    = lane >> 2;
    const int tq   = lane & 3;

    const size_t qbase = ((size_t)bh * SEQ + (size_t)nt * (128 * ONS)) * DIM;
    const float4* __restrict__ Qp4 = (const float4*)(Qin + qbase);
    float* __restrict__ Op = Out + qbase;

    {
        const uint4* __restrict__ Bg = (const uint4*)&g_kvh[bh][0][0];
        uint4* Bsv = (uint4*)&Bs[0][0];
        for (int i = tid; i < BS_BYTES / 16; i += 256) Bsv[i] = Bg[i];
    }

    float4 qreg[8];
#pragma unroll
    for (int j = 0; j < 8; j++) qreg[j] = Qp4[tid + j * 256];

    for (int s = 0; s < ONS; ++s) {
        const int p = s & 1;
        __half* qf = qfB + p * (128 * QF_STRIDE);

#pragma unroll
        for (int j = 0; j < 8; j++) {
            int i = tid + j * 256;
            int r = i >> 4, c4 = (i & 15) << 2;
            float4 q = qreg[j];
            __half2* qp = (__half2*)&qf[r * QF_STRIDE + c4];
            __half2* qn = (__half2*)&qf[r * QF_STRIDE + c4 + 64];
            qp[0] = __floats2half2_rn(fmaxf(q.x, 0.f), fmaxf(q.y, 0.f));
            qp[1] = __floats2half2_rn(fmaxf(q.z, 0.f), fmaxf(q.w, 0.f));
            qn[0] = __floats2half2_rn(fmaxf(-q.x, 0.f), fmaxf(-q.y, 0.f));
            qn[1] = __floats2half2_rn(fmaxf(-q.z, 0.f), fmaxf(-q.w, 0.f));
        }
        __syncthreads();   // the ONLY barrier: qf[p] complete (covers Bs on s==0)

        if (s + 1 < ONS) {
#pragma unroll
            for (int j = 0; j < 8; j++)
                qreg[j] = Qp4[(s + 1) * 2048 + tid + j * 256];
        }

        float c[9][4];
#pragma unroll
        for (int f = 0; f < 9; f++)
#pragma unroll
            for (int e = 0; e < 4; e++) c[f][e] = 0.0f;

#pragma unroll
        for (int ks = 0; ks < FEAT / 16; ++ks) {
            uint32_t a[4];
            {
                uint32_t addr = (uint32_t)__cvta_generic_to_shared(
                    &qf[(warp * 16 + (lane & 15)) * QF_STRIDE + ks * 16 + (lane >> 4) * 8]);
                asm volatile("ldmatrix.sync.aligned.m8n8.x4.shared.b16 {%0,%1,%2,%3}, [%4];"
                             : "=r"(a[0]), "=r"(a[1]), "=r"(a[2]), "=r"(a[3]) : "r"(addr));
            }
#pragma unroll
            for (int h = 0; h < 4; h++) {
                uint32_t b[4];
                uint32_t addr = (uint32_t)__cvta_generic_to_shared(
                    &Bs[ks * 16 + (lane & 15)][h * 16 + (lane >> 4) * 8]);
                asm volatile("ldmatrix.sync.aligned.m8n8.x4.trans.shared.b16 {%0,%1,%2,%3}, [%4];"
                             : "=r"(b[0]), "=r"(b[1]), "=r"(b[2]), "=r"(b[3]) : "r"(addr));
                asm volatile("mma.sync.aligned.m16n8k16.row.col.f32.f16.f16.f32 "
                             "{%0,%1,%2,%3},{%4,%5,%6,%7},{%8,%9},{%0,%1,%2,%3};"
                             : "+f"(c[h*2][0]), "+f"(c[h*2][1]), "+f"(c[h*2][2]), "+f"(c[h*2][3])
                             : "r"(a[0]), "r"(a[1]), "r"(a[2]), "r"(a[3]), "r"(b[0]), "r"(b[1]));
                asm volatile("mma.sync.aligned.m16n8k16.row.col.f32.f16.f16.f32 "
                             "{%0,%1,%2,%3},{%4,%5,%6,%7},{%8,%9},{%0,%1,%2,%3};"
                             : "+f"(c[h*2+1][0]), "+f"(c[h*2+1][1]), "+f"(c[h*2+1][2]), "+f"(c[h*2+1][3])
                             : "r"(a[0]), "r"(a[1]), "r"(a[2]), "r"(a[3]), "r"(b[2]), "r"(b[3]));
            }
            {   // Ksum tile: cols 64..71 (col 64 = normalizer)
                uint32_t b[2];
                uint32_t addr = (uint32_t)__cvta_generic_to_shared(
                    &Bs[ks * 16 + (lane & 15)][64]);
                asm volatile("ldmatrix.sync.aligned.m8n8.x2.trans.shared.b16 {%0,%1}, [%2];"
                             : "=r"(b[0]), "=r"(b[1]) : "r"(addr));
                asm volatile("mma.sync.aligned.m16n8k16.row.col.f32.f16.f16.f32 "
                             "{%0,%1,%2,%3},{%4,%5,%6,%7},{%8,%9},{%0,%1,%2,%3};"
                             : "+f"(c[8][0]), "+f"(c[8][1]), "+f"(c[8][2]), "+f"(c[8][3])
                             : "r"(a[0]), "r"(a[1]), "r"(a[2]), "r"(a[3]), "r"(b[0]), "r"(b[1]));
            }
        }

        float n_lo = __shfl_sync(0xffffffffu, c[8][0], lane & ~3);
        float n_hi = __shfl_sync(0xffffffffu, c[8][2], lane & ~3);
        float inv_lo = 1.0f / (n_lo + 1e-6f);
        float inv_hi = 1.0f / (n_hi + 1e-6f);

        // epilogue: cs strip aliases this warp's own qf[p] rows
        float* cw = reinterpret_cast<float*>(qf + (warp * 16) * QF_STRIDE);
#pragma unroll
        for (int f = 0; f < 8; f++) {
            int col = f * 8 + 2 * tq;
            *(float2*)&cw[g * CS_STRIDE + col] =
                make_float2(c[f][0] * inv_lo, c[f][1] * inv_lo);
            *(float2*)&cw[(g + 8) * CS_STRIDE + col] =
                make_float2(c[f][2] * inv_hi, c[f][3] * inv_hi);
        }
        __syncwarp();

        {
            float* orow = Op + ((size_t)s * 128 + warp * 16) * DIM;
#pragma unroll
            for (int it = 0; it < 8; ++it) {
                int idx = lane + it * 32;
                int r = idx >> 4, c4 = (idx & 15) << 2;
                float4 v = *(float4*)&cw[r * CS_STRIDE + c4];
                *(float4*)&orow[(size_t)r * DIM + c4] = v;
            }
        }
    }
}

// =====================================================================
extern "C" void kernel_launch(void* const* d_in, const int* in_sizes, int n_in,
                              void* d_out, int out_size) {
    const float* Q = (const float*)d_in[0];
    const float* K = (const float*)d_in[1];
    const float* V = (const float*)d_in[2];
    float* O = (float*)d_out;

    static int smem_set = 0;
    if (!smem_set) {
        cudaFuncSetAttribute(out_kernel, cudaFuncAttributeMaxDynamicSharedMemorySize, C_SMEM);
        smem_set = 1;
    }

    dim3 gA(NCHUNK, BH);
    kv_partial_kernel<<<gA, 256>>>(K, V);
    dim3 gB(BH, 8);
    kv_reduce_kernel<<<gB, 256>>>();
    dim3 gC(SEQ / (128 * ONS), BH);
    out_kernel<<<gC, 256, C_SMEM>>>(Q, O);
}

// round 17
// speedup vs baseline: 1.4651x; 1.0347x over previous
#include <cuda_runtime.h>
#include <cuda_fp16.h>
#include <mma.h>
#include <cstdint>

using namespace nvcuda;

#define BH      64        // batch*heads
#define SEQ     8192
#define DIM     64        // head dim
#define FEAT    128       // 2*DIM feature dim
#define NCHUNK  16
#define CHUNK   (SEQ / NCHUNK)   // 512 rows per reduction chunk
#define SUB     64               // rows staged in smem per iteration
#define BW      80               // partial width: 64 KV cols + 1 Ksum + 15 pad
#define BSW     88               // reduced B width (stride 176B, conflict-free)

// ---- scratch (device globals: no allocation allowed) ----
__device__ __align__(16) __half g_kv_part[NCHUNK][BH][FEAT][BW];  // fp16 partials
__device__ __align__(32) __half g_kvh[BH][FEAT][BSW];             // reduced fp16 B (col64 = Ksum)

// =====================================================================
// Kernel A: partial [KV | Ksum] = phi(K)^T @ [V | 1 | 0] over a chunk.
// Register double-buffered pipeline; fp16 epilogue via smem bounce.
// grid (NCHUNK, BH), 256 threads. (validated R16 version)
// =====================================================================
__global__ __launch_bounds__(256) void kv_partial_kernel(const float* __restrict__ Kin,
                                                         const float* __restrict__ Vin) {
    const int chunk = blockIdx.x;
    const int bh    = blockIdx.y;
    const int tid   = threadIdx.x;
    const int warp  = tid >> 5;
    const int lane  = tid & 31;
    const int wd    = warp >> 1;   // 0..3 -> 32 feature rows each
    const int wm    = warp & 1;    // 0..1 -> 32 V cols each

    __shared__ __align__(16) __half Kf_s[SUB][136];
    __shared__ __align__(16) __half V_s [SUB][88];

    for (int r = tid; r < SUB; r += 256) {
        V_s[r][64] = __float2half(1.0f);
#pragma unroll
        for (int p = 65; p < 80; p++) V_s[r][p] = __float2half(0.0f);
    }

    wmma::fragment<wmma::accumulator, 16, 16, 16, float> acc[4];
    wmma::fragment<wmma::accumulator, 16, 16, 16, float> accs[2];
#pragma unroll
    for (int i = 0; i < 4; i++) wmma::fill_fragment(acc[i], 0.0f);
#pragma unroll
    for (int i = 0; i < 2; i++) wmma::fill_fragment(accs[i], 0.0f);

    const size_t base = ((size_t)bh * SEQ + (size_t)chunk * CHUNK) * DIM;
    const float4* __restrict__ Kp4 = (const float4*)(Kin + base);
    const float4* __restrict__ Vp4 = (const float4*)(Vin + base);

    const int NF4 = SUB * 16;
    float4 kreg[4], vreg[4];

#pragma unroll
    for (int j = 0; j < 4; j++) {
        int i = tid + j * 256;
        kreg[j] = Kp4[i];
        vreg[j] = Vp4[i];
    }

    for (int sub = 0; sub < CHUNK / SUB; ++sub) {
#pragma unroll
        for (int j = 0; j < 4; j++) {
            int i = tid + j * 256;
            int r = i >> 4, c4 = (i & 15) << 2;
            float4 k = kreg[j], v = vreg[j];
            __half2* kp = (__half2*)&Kf_s[r][c4];
            __half2* kn = (__half2*)&Kf_s[r][c4 + 64];
            __half2* vp = (__half2*)&V_s[r][c4];
            kp[0] = __floats2half2_rn(fmaxf(k.x, 0.f), fmaxf(k.y, 0.f));
            kp[1] = __floats2half2_rn(fmaxf(k.z, 0.f), fmaxf(k.w, 0.f));
            kn[0] = __floats2half2_rn(fmaxf(-k.x, 0.f), fmaxf(-k.y, 0.f));
            kn[1] = __floats2half2_rn(fmaxf(-k.z, 0.f), fmaxf(-k.w, 0.f));
            vp[0] = __floats2half2_rn(v.x, v.y);
            vp[1] = __floats2half2_rn(v.z, v.w);
        }
        __syncthreads();

        if (sub + 1 < CHUNK / SUB) {
#pragma unroll
            for (int j = 0; j < 4; j++) {
                int i = tid + j * 256;
                kreg[j] = Kp4[(sub + 1) * NF4 + i];
                vreg[j] = Vp4[(sub + 1) * NF4 + i];
            }
        }

#pragma unroll
        for (int ks = 0; ks < SUB / 16; ++ks) {
            wmma::fragment<wmma::matrix_a, 16, 16, 16, __half, wmma::col_major> a0, a1;
            wmma::fragment<wmma::matrix_b, 16, 16, 16, __half, wmma::row_major> b0, b1;
            wmma::load_matrix_sync(a0, &Kf_s[ks * 16][wd * 32],      136);
            wmma::load_matrix_sync(a1, &Kf_s[ks * 16][wd * 32 + 16], 136);
            wmma::load_matrix_sync(b0, &V_s[ks * 16][wm * 32],       88);
            wmma::load_matrix_sync(b1, &V_s[ks * 16][wm * 32 + 16],  88);
            wmma::mma_sync(acc[0], a0, b0, acc[0]);
            wmma::mma_sync(acc[1], a0, b1, acc[1]);
            wmma::mma_sync(acc[2], a1, b0, acc[2]);
            wmma::mma_sync(acc[3], a1, b1, acc[3]);
            if (wm == 0) {
                wmma::fragment<wmma::matrix_b, 16, 16, 16, __half, wmma::row_major> b2;
                wmma::load_matrix_sync(b2, &V_s[ks * 16][64], 88);
                wmma::mma_sync(accs[0], a0, b2, accs[0]);
                wmma::mma_sync(accs[1], a1, b2, accs[1]);
            }
        }
        __syncthreads();
    }

    // ---- epilogue: fp32 accum -> per-warp smem scratch -> fp16 STG.128 ----
    float* scr = reinterpret_cast<float*>(&Kf_s[0][0]) + warp * 264;
    __half* op = &g_kv_part[chunk][bh][0][0];
    const int r_  = lane >> 1;
    const int c0_ = (lane & 1) * 8;

#pragma unroll
    for (int ti = 0; ti < 2; ++ti)
#pragma unroll
        for (int tj = 0; tj < 2; ++tj) {
            wmma::store_matrix_sync(scr, acc[ti * 2 + tj], 16, wmma::mem_row_major);
            __syncwarp();
            __half2 h[4];
#pragma unroll
            for (int t = 0; t < 4; t++)
                h[t] = __floats2half2_rn(scr[r_ * 16 + c0_ + 2 * t],
                                         scr[r_ * 16 + c0_ + 2 * t + 1]);
            *(uint4*)&op[(size_t)(wd * 32 + ti * 16 + r_) * BW + wm * 32 + tj * 16 + c0_] =
                *(uint4*)h;
            __syncwarp();
        }
    if (wm == 0) {
#pragma unroll
        for (int ti = 0; ti < 2; ++ti) {
            wmma::store_matrix_sync(scr, accs[ti], 16, wmma::mem_row_major);
            __syncwarp();
            __half2 h[4];
#pragma unroll
            for (int t = 0; t < 4; t++)
                h[t] = __floats2half2_rn(scr[r_ * 16 + c0_ + 2 * t],
                                         scr[r_ * 16 + c0_ + 2 * t + 1]);
            *(uint4*)&op[(size_t)(wd * 32 + ti * 16 + r_) * BW + 64 + c0_] = *(uint4*)h;
            __syncwarp();
        }
    }
}

// =====================================================================
// Kernel B: reduce fp16 chunk partials -> fp16 B matrix [128 x 88]
// (cols 0..63 = KV, col 64 = Ksum, 65..87 = 0). grid (BH, 8), 256 thr.
// =====================================================================
__global__ __launch_bounds__(256) void kv_reduce_kernel() {
    const int bh    = blockIdx.x;
    const int dbase = blockIdx.y * 16;
    const int tid   = threadIdx.x;

    for (int idx = tid; idx < 16 * 33; idx += 256) {
        int d = dbase + idx / 33, m2 = idx % 33;
        float2 s = make_float2(0.0f, 0.0f);
#pragma unroll
        for (int c = 0; c < NCHUNK; c++) {
            float2 f = __half22float2(*(const __half2*)&g_kv_part[c][bh][d][m2 * 2]);
            s.x += f.x; s.y += f.y;
        }
        if (m2 < 32) {
            *(__half2*)&g_kvh[bh][d][m2 * 2] = __floats2half2_rn(s.x, s.y);
        } else {
            *(__half2*)&g_kvh[bh][d][64] = __floats2half2_rn(s.x, 0.0f);
        }
    }
    for (int idx = tid; idx < 16 * 22; idx += 256) {
        int d = dbase + idx / 22, m = 66 + idx % 22;
        g_kvh[bh][d][m] = __float2half(0.0f);
    }
}

// =====================================================================
// Kernel C: 128 threads (4 warps), 64 Q rows per CTA, ONE tile per CTA
// -> 4 CTAs/SM, latency hidden by CTA-level parallelism.
// Warp w owns rows [w*16, w*16+16), all 72 cols (incl. Ksum col 64).
// Static smem: qf[64][136] (17408B) + Bs[128][88] (22528B) = 39936B.
// grid (SEQ/64, BH).
// =====================================================================
#define QF_STRIDE 136
#define CS_STRIDE 68

__global__ __launch_bounds__(128, 4) void out_kernel(const float* __restrict__ Qin,
                                                     float* __restrict__ Out) {
    __shared__ __align__(16) __half qf[64][QF_STRIDE];
    __shared__ __align__(16) __half Bs[FEAT][BSW];

    const int nt   = blockIdx.x;
    const int bh   = blockIdx.y;
    const int tid  = threadIdx.x;
    const int warp = tid >> 5;
    const int lane = tid & 31;
    const int g    = lane >> 2;
    const int tq   = lane & 3;

    const size_t qbase = ((size_t)bh * SEQ + (size_t)nt * 64) * DIM;
    const float4* __restrict__ Qp4 = (const float4*)(Qin + qbase);
    float* __restrict__ Op = Out + qbase;

    // load Q into registers (kicks off DRAM early)
    float4 qreg[8];
#pragma unroll
    for (int j = 0; j < 8; j++) qreg[j] = Qp4[tid + j * 128];

    // stage B (L2-resident; coalesced uint4)
    {
        const uint4* __restrict__ Bg = (const uint4*)&g_kvh[bh][0][0];
        uint4* Bsv = (uint4*)&Bs[0][0];
#pragma unroll
        for (int j = 0; j < 11; j++) Bsv[tid + j * 128] = Bg[tid + j * 128];
    }

    // convert qreg -> qf (phi transform)
#pragma unroll
    for (int j = 0; j < 8; j++) {
        int i = tid + j * 128;
        int r = i >> 4, c4 = (i & 15) << 2;
        float4 q = qreg[j];
        __half2* qp = (__half2*)&qf[r][c4];
        __half2* qn = (__half2*)&qf[r][c4 + 64];
        qp[0] = __floats2half2_rn(fmaxf(q.x, 0.f), fmaxf(q.y, 0.f));
        qp[1] = __floats2half2_rn(fmaxf(q.z, 0.f), fmaxf(q.w, 0.f));
        qn[0] = __floats2half2_rn(fmaxf(-q.x, 0.f), fmaxf(-q.y, 0.f));
        qn[1] = __floats2half2_rn(fmaxf(-q.z, 0.f), fmaxf(-q.w, 0.f));
    }
    __syncthreads();   // qf + Bs ready

    // ---- warp-local MMA: 16 rows x 72 cols over k=128 ----
    float c[9][4];
#pragma unroll
    for (int f = 0; f < 9; f++)
#pragma unroll
        for (int e = 0; e < 4; e++) c[f][e] = 0.0f;

#pragma unroll
    for (int ks = 0; ks < FEAT / 16; ++ks) {
        uint32_t a[4];
        {
            uint32_t addr = (uint32_t)__cvta_generic_to_shared(
                &qf[warp * 16 + (lane & 15)][ks * 16 + (lane >> 4) * 8]);
            asm volatile("ldmatrix.sync.aligned.m8n8.x4.shared.b16 {%0,%1,%2,%3}, [%4];"
                         : "=r"(a[0]), "=r"(a[1]), "=r"(a[2]), "=r"(a[3]) : "r"(addr));
        }
#pragma unroll
        for (int h = 0; h < 4; h++) {
            uint32_t b[4];
            uint32_t addr = (uint32_t)__cvta_generic_to_shared(
                &Bs[ks * 16 + (lane & 15)][h * 16 + (lane >> 4) * 8]);
            asm volatile("ldmatrix.sync.aligned.m8n8.x4.trans.shared.b16 {%0,%1,%2,%3}, [%4];"
                         : "=r"(b[0]), "=r"(b[1]), "=r"(b[2]), "=r"(b[3]) : "r"(addr));
            asm volatile("mma.sync.aligned.m16n8k16.row.col.f32.f16.f16.f32 "
                         "{%0,%1,%2,%3},{%4,%5,%6,%7},{%8,%9},{%0,%1,%2,%3};"
                         : "+f"(c[h*2][0]), "+f"(c[h*2][1]), "+f"(c[h*2][2]), "+f"(c[h*2][3])
                         : "r"(a[0]), "r"(a[1]), "r"(a[2]), "r"(a[3]), "r"(b[0]), "r"(b[1]));
            asm volatile("mma.sync.aligned.m16n8k16.row.col.f32.f16.f16.f32 "
                         "{%0,%1,%2,%3},{%4,%5,%6,%7},{%8,%9},{%0,%1,%2,%3};"
                         : "+f"(c[h*2+1][0]), "+f"(c[h*2+1][1]), "+f"(c[h*2+1][2]), "+f"(c[h*2+1][3])
                         : "r"(a[0]), "r"(a[1]), "r"(a[2]), "r"(a[3]), "r"(b[2]), "r"(b[3]));
        }
        {   // Ksum tile: cols 64..71 (col 64 = normalizer)
            uint32_t b[2];
            uint32_t addr = (uint32_t)__cvta_generic_to_shared(
                &Bs[ks * 16 + (lane & 15)][64]);
            asm volatile("ldmatrix.sync.aligned.m8n8.x2.trans.shared.b16 {%0,%1}, [%2];"
                         : "=r"(b[0]), "=r"(b[1]) : "r"(addr));
            asm volatile("mma.sync.aligned.m16n8k16.row.col.f32.f16.f16.f32 "
                         "{%0,%1,%2,%3},{%4,%5,%6,%7},{%8,%9},{%0,%1,%2,%3};"
                         : "+f"(c[8][0]), "+f"(c[8][1]), "+f"(c[8][2]), "+f"(c[8][3])
                         : "r"(a[0]), "r"(a[1]), "r"(a[2]), "r"(a[3]), "r"(b[0]), "r"(b[1]));
        }
    }

    // ---- normalizer from own accumulators (col 64 held by tq==0) ----
    float n_lo = __shfl_sync(0xffffffffu, c[8][0], lane & ~3);
    float n_hi = __shfl_sync(0xffffffffu, c[8][2], lane & ~3);
    float inv_lo = 1.0f / (n_lo + 1e-6f);
    float inv_hi = 1.0f / (n_hi + 1e-6f);

    // ---- epilogue: cs strip aliases this warp's own qf rows ----
    // (MMA done reading them; only this warp ever reads those rows)
    float* cw = reinterpret_cast<float*>(&qf[warp * 16][0]);
#pragma unroll
    for (int f = 0; f < 8; f++) {
        int col = f * 8 + 2 * tq;
        *(float2*)&cw[g * CS_STRIDE + col] =
            make_float2(c[f][0] * inv_lo, c[f][1] * inv_lo);
        *(float2*)&cw[(g + 8) * CS_STRIDE + col] =
            make_float2(c[f][2] * inv_hi, c[f][3] * inv_hi);
    }
    __syncwarp();

    // coalesced float4 read-back + STG (16 rows x 256B contiguous)
    {
        float* orow = Op + (size_t)(warp * 16) * DIM;
#pragma unroll
        for (int it = 0; it < 8; ++it) {
            int idx = lane + it * 32;
            int r = idx >> 4, c4 = (idx & 15) << 2;
            float4 v = *(float4*)&cw[r * CS_STRIDE + c4];
            *(float4*)&orow[(size_t)r * DIM + c4] = v;
        }
    }
}

// =====================================================================
extern "C" void kernel_launch(void* const* d_in, const int* in_sizes, int n_in,
                              void* d_out, int out_size) {
    const float* Q = (const float*)d_in[0];
    const float* K = (const float*)d_in[1];
    const float* V = (const float*)d_in[2];
    float* O = (float*)d_out;

    dim3 gA(NCHUNK, BH);
    kv_partial_kernel<<<gA, 256>>>(K, V);
    dim3 gB(BH, 8);
    kv_reduce_kernel<<<gB, 256>>>();
    dim3 gC(SEQ / 64, BH);
    out_kernel<<<gC, 128>>>(Q, O);
}